// round 2
// baseline (speedup 1.0000x reference)
#include <cuda_runtime.h>
#include <cstddef>

// CrossLevelAttention: out[b,t,h*64+d] = sum_l w_l * softmax_l(Q K_l^T * scale) V_l
// Levels: l0 causal Tm=T(2048), l1 Tm=512, l2 Tm=128. w = softmax(level_logits).
// fp32 SIMT flash-attention, one query per thread, 64-key smem tiles.

#define NHEAD 16
#define DH 64
#define CDIM (NHEAD * DH)
#define BLOCK_M 128
#define BLOCK_N 64
#define SCALE 0.125f  // 64^-0.5

template <bool CAUSAL>
__device__ __forceinline__ void attend_level(
    const float* __restrict__ Kl, const float* __restrict__ Vl,
    int Tm, int b, int h, int qidx, int n_keys,
    const float (&q)[DH], float (&acc)[DH], float& lsum,
    float4* __restrict__ kbuf, float4* __restrict__ vbuf, int tid)
{
    lsum = 0.f;
    #pragma unroll
    for (int d = 0; d < DH; d++) acc[d] = 0.f;

    for (int kt = 0; kt < n_keys; kt += BLOCK_N) {
        __syncthreads();  // protect previous tile's readers
        // Cooperative load of K,V tile [BLOCK_N x DH] as float4.
        #pragma unroll
        for (int it = 0; it < (BLOCK_N * (DH / 4)) / BLOCK_M; it++) {
            int idx = it * BLOCK_M + tid;          // 0..1023
            int row = idx >> 4;                     // key within tile
            int col = idx & 15;                     // float4 within row
            size_t g = ((size_t)b * Tm + (size_t)(kt + row)) * CDIM
                     + (size_t)h * DH + (size_t)col * 4;
            kbuf[idx] = *reinterpret_cast<const float4*>(Kl + g);
            vbuf[idx] = *reinterpret_cast<const float4*>(Vl + g);
        }
        __syncthreads();

        #pragma unroll 2
        for (int j = 0; j < BLOCK_N; j++) {
            float s0 = 0.f, s1 = 0.f, s2 = 0.f, s3 = 0.f;
            #pragma unroll
            for (int d4 = 0; d4 < 16; d4++) {
                float4 k4 = kbuf[j * 16 + d4];
                s0 = fmaf(q[4 * d4 + 0], k4.x, s0);
                s1 = fmaf(q[4 * d4 + 1], k4.y, s1);
                s2 = fmaf(q[4 * d4 + 2], k4.z, s2);
                s3 = fmaf(q[4 * d4 + 3], k4.w, s3);
            }
            float s = (s0 + s1) + (s2 + s3);
            float p = __expf(s);
            if (CAUSAL && (kt + j) > qidx) p = 0.f;
            lsum += p;
            #pragma unroll
            for (int d4 = 0; d4 < 16; d4++) {
                float4 v4 = vbuf[j * 16 + d4];
                acc[4 * d4 + 0] = fmaf(p, v4.x, acc[4 * d4 + 0]);
                acc[4 * d4 + 1] = fmaf(p, v4.y, acc[4 * d4 + 1]);
                acc[4 * d4 + 2] = fmaf(p, v4.z, acc[4 * d4 + 2]);
                acc[4 * d4 + 3] = fmaf(p, v4.w, acc[4 * d4 + 3]);
            }
        }
    }
}

__global__ __launch_bounds__(BLOCK_M, 2)
void xlvl_attn_kernel(
    const float* __restrict__ Q,
    const float* __restrict__ K0, const float* __restrict__ V0,
    const float* __restrict__ K1, const float* __restrict__ V1,
    const float* __restrict__ K2, const float* __restrict__ V2,
    const float* __restrict__ logits,
    float* __restrict__ out,
    int T, int T1, int T2)
{
    __shared__ float4 kbuf[BLOCK_N * (DH / 4)];
    __shared__ float4 vbuf[BLOCK_N * (DH / 4)];

    // Reverse q-block order so heaviest (most causal keys) CTAs launch first.
    const int qb  = (int)(gridDim.x - 1 - blockIdx.x);
    const int h   = blockIdx.y;
    const int b   = blockIdx.z;
    const int tid = threadIdx.x;
    const int q0  = qb * BLOCK_M;
    const int qidx = q0 + tid;

    // Level weights: softmax(level_logits)
    float l0 = logits[0], l1 = logits[1], l2 = logits[2];
    float mx = fmaxf(l0, fmaxf(l1, l2));
    float e0 = __expf(l0 - mx), e1 = __expf(l1 - mx), e2 = __expf(l2 - mx);
    float winv = 1.0f / (e0 + e1 + e2);
    float w0 = e0 * winv, w1 = e1 * winv, w2 = e2 * winv;

    // Load this thread's query row, fold in SCALE.
    float q[DH];
    {
        const float4* qsrc = reinterpret_cast<const float4*>(
            Q + (((size_t)b * NHEAD + h) * (size_t)T + qidx) * DH);
        #pragma unroll
        for (int i = 0; i < 16; i++) {
            float4 v = qsrc[i];
            q[4 * i + 0] = v.x * SCALE;
            q[4 * i + 1] = v.y * SCALE;
            q[4 * i + 2] = v.z * SCALE;
            q[4 * i + 3] = v.w * SCALE;
        }
    }

    float total[DH];
    float acc[DH];
    float lsum;

    // Level 0: causal over T keys (only up to this q-block's end).
    attend_level<true>(K0, V0, T, b, h, qidx, q0 + BLOCK_M, q, acc, lsum, kbuf, vbuf, tid);
    {
        float inv = w0 / lsum;
        #pragma unroll
        for (int d = 0; d < DH; d++) total[d] = acc[d] * inv;
    }

    // Level 1: full 512 keys.
    attend_level<false>(K1, V1, T1, b, h, qidx, T1, q, acc, lsum, kbuf, vbuf, tid);
    {
        float inv = w1 / lsum;
        #pragma unroll
        for (int d = 0; d < DH; d++) total[d] = fmaf(acc[d], inv, total[d]);
    }

    // Level 2: full 128 keys.
    attend_level<false>(K2, V2, T2, b, h, qidx, T2, q, acc, lsum, kbuf, vbuf, tid);
    {
        float inv = w2 / lsum;
        #pragma unroll
        for (int d = 0; d < DH; d++) total[d] = fmaf(acc[d], inv, total[d]);
    }

    // Write out[b, t, h*64 + d]
    float4* dst = reinterpret_cast<float4*>(
        out + ((size_t)b * T + qidx) * CDIM + (size_t)h * DH);
    #pragma unroll
    for (int i = 0; i < 16; i++) {
        float4 v;
        v.x = total[4 * i + 0];
        v.y = total[4 * i + 1];
        v.z = total[4 * i + 2];
        v.w = total[4 * i + 3];
        dst[i] = v;
    }
}

extern "C" void kernel_launch(void* const* d_in, const int* in_sizes, int n_in,
                              void* d_out, int out_size)
{
    const float* Q      = (const float*)d_in[0];
    const float* K0     = (const float*)d_in[1];
    const float* V0     = (const float*)d_in[2];
    const float* K1     = (const float*)d_in[3];
    const float* V1     = (const float*)d_in[4];
    const float* K2     = (const float*)d_in[5];
    const float* V2     = (const float*)d_in[6];
    const float* logits = (const float*)d_in[7];
    float* out          = (float*)d_out;

    const int B  = 2;
    const int T  = in_sizes[1] / (B * CDIM);   // K0: [B, T, C]
    const int T1 = in_sizes[3] / (B * CDIM);   // K1: [B, 512, C]
    const int T2 = in_sizes[5] / (B * CDIM);   // K2: [B, 128, C]

    dim3 grid(T / BLOCK_M, NHEAD, B);
    xlvl_attn_kernel<<<grid, BLOCK_M>>>(Q, K0, V0, K1, V1, K2, V2, logits, out,
                                        T, T1, T2);
}